// round 9
// baseline (speedup 1.0000x reference)
#include <cuda_runtime.h>
#include <cuda_fp16.h>
#include <cstdint>

// Problem constants (fixed shapes)
#define NNODES 100000
#define NEDGES 3200000
#define C 128           // feature dim (in = hid = out = 128)
#define NSCAN_BLOCKS ((NNODES + 1023) / 1024)   // 98

// ---------------- scratch (static device globals; no allocation) ----------------
__device__ __align__(16) int g_csr[NEDGES];
__device__ __align__(16) int g_rank[NEDGES];
__device__ int    g_cnt[NNODES];
__device__ int    g_rowptr[NNODES + 1];
__device__ int    g_scanAgg[NSCAN_BLOCKS];      // block aggregates
__device__ int    g_scanInc[NSCAN_BLOCKS];      // inclusive prefixes
__device__ int    g_scanFlag[NSCAN_BLOCKS];     // 0=none, 1=agg ready, 2=inclusive ready
__device__ float  g_dinv[NNODES];
__device__ __align__(16) __half g_h[(size_t)NNODES * C];    // dinv-prescaled GEMM out, fp16
__device__ __align__(16) __half g_buf[(size_t)NNODES * C];  // layer-1 agg+relu out, fp16

// dynamic shared memory for the tensor-core GEMM:
//   Xs  : 128 rows x 136 halves (padded: 272B row stride -> conflict-free ldmatrix)
//   Wts : 128 rows x 136 halves
extern __shared__ __align__(16) __half g_smem[];
#define XS_STRIDE 136
#define WTS_OFF   (128 * XS_STRIDE)
#define GEMM_SMEM_BYTES (2 * 128 * XS_STRIDE * (int)sizeof(__half))

// ---------------- mma helpers ----------------
__device__ __forceinline__ unsigned sptr(const void* p) {
    return (unsigned)__cvta_generic_to_shared(p);
}
__device__ __forceinline__ void ldsm_x4(unsigned& r0, unsigned& r1,
                                        unsigned& r2, unsigned& r3, unsigned addr) {
    asm volatile("ldmatrix.sync.aligned.m8n8.x4.shared.b16 {%0,%1,%2,%3}, [%4];"
                 : "=r"(r0), "=r"(r1), "=r"(r2), "=r"(r3) : "r"(addr));
}
__device__ __forceinline__ void mma16816(float& d0, float& d1, float& d2, float& d3,
                                         unsigned a0, unsigned a1, unsigned a2, unsigned a3,
                                         unsigned b0, unsigned b1) {
    asm volatile(
        "mma.sync.aligned.m16n8k16.row.col.f32.f16.f16.f32 "
        "{%0,%1,%2,%3},{%4,%5,%6,%7},{%8,%9},{%0,%1,%2,%3};"
        : "+f"(d0), "+f"(d1), "+f"(d2), "+f"(d3)
        : "r"(a0), "r"(a1), "r"(a2), "r"(a3), "r"(b0), "r"(b1));
}

// ---------------- prologue kernels ----------------

__global__ void zero_kernel(int n) {
    int i = blockIdx.x * blockDim.x + threadIdx.x;
    if (i < n) g_cnt[i] = 0;
    if (i < NSCAN_BLOCKS) g_scanFlag[i] = 0;
}

// histogram of dst degree + per-edge rank (4 edges per thread)
__global__ void hist_kernel(const int* __restrict__ ei, int nedges) {
    int t = blockIdx.x * blockDim.x + threadIdx.x;
    int e = t * 4;
    if (e + 4 <= nedges) {
        int4 d4 = *(const int4*)&ei[nedges + e];
        int4 r4;
        r4.x = atomicAdd(&g_cnt[d4.x], 1);
        r4.y = atomicAdd(&g_cnt[d4.y], 1);
        r4.z = atomicAdd(&g_cnt[d4.z], 1);
        r4.w = atomicAdd(&g_cnt[d4.w], 1);
        *(int4*)&g_rank[e] = r4;
    } else {
        for (int k = e; k < nedges; k++)
            g_rank[k] = atomicAdd(&g_cnt[ei[nedges + k]], 1);
    }
}

// single-pass exclusive scan (decoupled lookback) + dinv + rowptr[n]
__global__ __launch_bounds__(1024) void scan_kernel(int n) {
    __shared__ int warp_sums[32];
    __shared__ int s_agg;
    __shared__ int s_prefix;
    const int tid = threadIdx.x, lane = tid & 31, wid = tid >> 5;
    const int b = blockIdx.x;
    const int i = b * 1024 + tid;
    int v = (i < n) ? g_cnt[i] : 0;
    int x = v;
    #pragma unroll
    for (int off = 1; off < 32; off <<= 1) {
        int t = __shfl_up_sync(0xffffffffu, x, off);
        if (lane >= off) x += t;
    }
    if (lane == 31) warp_sums[wid] = x;
    __syncthreads();
    if (wid == 0) {
        int ws = warp_sums[lane];
        #pragma unroll
        for (int off = 1; off < 32; off <<= 1) {
            int t = __shfl_up_sync(0xffffffffu, ws, off);
            if (lane >= off) ws += t;
        }
        warp_sums[lane] = ws;
    }
    __syncthreads();
    int woff = wid ? warp_sums[wid - 1] : 0;
    if (tid == 1023) s_agg = woff + x;   // block total
    __syncthreads();

    if (tid == 0) {
        int agg = s_agg;
        g_scanAgg[b] = agg;
        __threadfence();
        g_scanFlag[b] = 1;
        // lookback
        int prefix = 0;
        volatile int* flags = g_scanFlag;
        for (int p = b - 1; p >= 0; p--) {
            int f;
            while ((f = flags[p]) == 0) {}
            if (f == 2) { prefix += g_scanInc[p]; break; }
            prefix += g_scanAgg[p];
        }
        g_scanInc[b] = prefix + agg;
        __threadfence();
        g_scanFlag[b] = 2;
        s_prefix = prefix;
    }
    __syncthreads();
    int prefix = s_prefix;
    if (i < n) {
        g_rowptr[i] = prefix + woff + x - v;     // global exclusive
        g_dinv[i] = rsqrtf((float)(v + 1));      // deg = in-deg + self loop
    }
    if (b == gridDim.x - 1 && tid == 1023) g_rowptr[n] = prefix + s_agg;
}

// fill CSR atomic-free using precomputed ranks (4 edges per thread)
__global__ void fill_kernel(const int* __restrict__ ei, int nedges) {
    int t = blockIdx.x * blockDim.x + threadIdx.x;
    int e = t * 4;
    if (e + 4 <= nedges) {
        int4 s4 = *(const int4*)&ei[e];
        int4 d4 = *(const int4*)&ei[nedges + e];
        int4 r4 = *(const int4*)&g_rank[e];
        g_csr[g_rowptr[d4.x] + r4.x] = s4.x;
        g_csr[g_rowptr[d4.y] + r4.y] = s4.y;
        g_csr[g_rowptr[d4.z] + r4.z] = s4.z;
        g_csr[g_rowptr[d4.w] + r4.w] = s4.w;
    } else {
        for (int k = e; k < nedges; k++)
            g_csr[g_rowptr[ei[nedges + k]] + g_rank[k]] = ei[k];
    }
}

// ---------------- GEMM (tensor core): g_h(fp16) = dinv ⊙ (X @ W) --------------
// Block: 128 rows x 128 cols, K=128 resident. 8 warps: 4 (m) x 2 (n).
// W (fp32 [k][n] in gmem) is transposed+converted into smem in-kernel.
template <int LAYER>
__global__ __launch_bounds__(256) void gemm_tc_kernel(
    const float* __restrict__ Xin, const float* __restrict__ W, int nrows) {
    __half* Xs  = g_smem;            // [128][136]
    __half* Wts = g_smem + WTS_OFF;  // [128][136]  (W^T: [n][k])
    const int tid  = threadIdx.x;
    const int lane = tid & 31;
    const int wid  = tid >> 5;
    const int row_blk = blockIdx.x * 128;

    // W fp32 [k][n] -> Wts fp16 [n][k]  (coalesced gmem read)
    #pragma unroll
    for (int i = tid; i < 16384; i += 256) {
        int k = i >> 7, nn = i & 127;
        Wts[nn * XS_STRIDE + k] = __float2half(W[i]);
    }
    // X rows into Xs
    if (LAYER == 1) {
        #pragma unroll
        for (int i = tid; i < 4096; i += 256) {       // 128 rows x 32 float4
            int r = i >> 5, j = i & 31;
            int gr = row_blk + r;
            float4 v = (gr < nrows) ? ((const float4*)&Xin[(size_t)gr * C])[j]
                                    : make_float4(0.f, 0.f, 0.f, 0.f);
            __half2 h0 = __floats2half2_rn(v.x, v.y);
            __half2 h1 = __floats2half2_rn(v.z, v.w);
            uint2 st;
            st.x = *(unsigned*)&h0;
            st.y = *(unsigned*)&h1;
            *(uint2*)&Xs[r * XS_STRIDE + j * 4] = st;
        }
    } else {
        #pragma unroll
        for (int i = tid; i < 2048; i += 256) {       // 128 rows x 16 uint4 (fp16)
            int r = i >> 4, j = i & 15;
            int gr = row_blk + r;
            uint4 v = (gr < nrows) ? *(const uint4*)&g_buf[(size_t)gr * C + j * 8]
                                   : make_uint4(0u, 0u, 0u, 0u);
            *(uint4*)&Xs[r * XS_STRIDE + j * 8] = v;
        }
    }
    __syncthreads();

    const int warp_m = wid & 3;        // 4 m-warps -> 32 rows each
    const int warp_n = wid >> 2;       // 2 n-warps -> 64 cols each
    const int m0 = warp_m * 32;
    const int n0 = warp_n * 64;

    float acc[2][8][4];
    #pragma unroll
    for (int mt = 0; mt < 2; mt++)
        #pragma unroll
        for (int nt = 0; nt < 8; nt++)
            #pragma unroll
            for (int q = 0; q < 4; q++) acc[mt][nt][q] = 0.f;

    #pragma unroll
    for (int ks = 0; ks < 8; ks++) {
        const int k0 = ks * 16;
        unsigned A0[4], A1[4];
        {
            const __half* p0 = &Xs[(m0 + 0 + (lane & 15)) * XS_STRIDE + k0 + (lane >> 4) * 8];
            ldsm_x4(A0[0], A0[1], A0[2], A0[3], sptr(p0));
            const __half* p1 = &Xs[(m0 + 16 + (lane & 15)) * XS_STRIDE + k0 + (lane >> 4) * 8];
            ldsm_x4(A1[0], A1[1], A1[2], A1[3], sptr(p1));
        }
        // B: Wts is [n][k] row-major == ".col" B operand -> NON-trans ldmatrix
        unsigned Bf[8][2];
        #pragma unroll
        for (int np = 0; np < 4; np++) {
            int g = lane >> 3;
            const __half* p = &Wts[(n0 + np * 16 + (g >> 1) * 8 + (lane & 7)) * XS_STRIDE
                                   + k0 + (g & 1) * 8];
            unsigned t0, t1, t2, t3;
            ldsm_x4(t0, t1, t2, t3, sptr(p));
            Bf[2 * np + 0][0] = t0; Bf[2 * np + 0][1] = t1;
            Bf[2 * np + 1][0] = t2; Bf[2 * np + 1][1] = t3;
        }
        #pragma unroll
        for (int nt = 0; nt < 8; nt++) {
            mma16816(acc[0][nt][0], acc[0][nt][1], acc[0][nt][2], acc[0][nt][3],
                     A0[0], A0[1], A0[2], A0[3], Bf[nt][0], Bf[nt][1]);
            mma16816(acc[1][nt][0], acc[1][nt][1], acc[1][nt][2], acc[1][nt][3],
                     A1[0], A1[1], A1[2], A1[3], Bf[nt][0], Bf[nt][1]);
        }
    }

    // epilogue: scale row by dinv, store fp16
    #pragma unroll
    for (int mt = 0; mt < 2; mt++) {
        int r0 = row_blk + m0 + mt * 16 + (lane >> 2);
        int r1 = r0 + 8;
        float di0 = (r0 < nrows) ? g_dinv[r0] : 0.f;
        float di1 = (r1 < nrows) ? g_dinv[r1] : 0.f;
        #pragma unroll
        for (int nt = 0; nt < 8; nt++) {
            int col = n0 + nt * 8 + (lane & 3) * 2;
            if (r0 < nrows) {
                __half2 h = __floats2half2_rn(acc[mt][nt][0] * di0, acc[mt][nt][1] * di0);
                *(unsigned*)&g_h[(size_t)r0 * C + col] = *(unsigned*)&h;
            }
            if (r1 < nrows) {
                __half2 h = __floats2half2_rn(acc[mt][nt][2] * di1, acc[mt][nt][3] * di1);
                *(unsigned*)&g_h[(size_t)r1 * C + col] = *(unsigned*)&h;
            }
        }
    }
}

// ---------------- SpMM: warp-per-destination-row, weight-free gather ----------
// out[d] = dinv[d] * ( sum_{e in row d} h'[src_e] + h'[d] ) + bias
// LAYER=1: writes g_buf fp16 (+relu). LAYER=2: writes param out fp32.
template <int LAYER>
__global__ __launch_bounds__(256) void spmm_kernel(
    const float* __restrict__ bias, float* __restrict__ outp, int n) {
    int warp = (blockIdx.x * blockDim.x + threadIdx.x) >> 5;
    int lane = threadIdx.x & 31;
    if (warp >= n) return;
    const uint2* __restrict__ H2 = (const uint2*)g_h;
    float dd = g_dinv[warp];

    float4 acc;
    {
        uint2 raw = __ldcg(&H2[(size_t)warp * 32 + lane]);  // self loop
        float2 f0 = __half22float2(*(const __half2*)&raw.x);
        float2 f1 = __half22float2(*(const __half2*)&raw.y);
        acc = make_float4(f0.x, f0.y, f1.x, f1.y);
    }
    int e0 = g_rowptr[warp];
    int e1 = g_rowptr[warp + 1];
    int e = e0;
    for (; e + 8 <= e1; e += 8) {
        uint2 r[8];
        #pragma unroll
        for (int j = 0; j < 8; j++) {
            int s = g_csr[e + j];
            r[j] = __ldcg(&H2[(size_t)s * 32 + lane]);
        }
        #pragma unroll
        for (int j = 0; j < 8; j++) {
            float2 f0 = __half22float2(*(const __half2*)&r[j].x);
            float2 f1 = __half22float2(*(const __half2*)&r[j].y);
            acc.x += f0.x; acc.y += f0.y; acc.z += f1.x; acc.w += f1.y;
        }
    }
    for (; e < e1; e++) {
        int s = g_csr[e];
        uint2 raw = __ldcg(&H2[(size_t)s * 32 + lane]);
        float2 f0 = __half22float2(*(const __half2*)&raw.x);
        float2 f1 = __half22float2(*(const __half2*)&raw.y);
        acc.x += f0.x; acc.y += f0.y; acc.z += f1.x; acc.w += f1.y;
    }
    float4 b = ((const float4*)bias)[lane];
    acc.x = acc.x * dd + b.x;
    acc.y = acc.y * dd + b.y;
    acc.z = acc.z * dd + b.z;
    acc.w = acc.w * dd + b.w;
    if (LAYER == 1) {
        acc.x = fmaxf(acc.x, 0.f);
        acc.y = fmaxf(acc.y, 0.f);
        acc.z = fmaxf(acc.z, 0.f);
        acc.w = fmaxf(acc.w, 0.f);
        __half2 h0 = __floats2half2_rn(acc.x, acc.y);
        __half2 h1 = __floats2half2_rn(acc.z, acc.w);
        uint2 st;
        st.x = *(unsigned*)&h0;
        st.y = *(unsigned*)&h1;
        ((uint2*)g_buf)[(size_t)warp * 32 + lane] = st;
    } else {
        ((float4*)outp)[(size_t)warp * 32 + lane] = acc;
    }
}

// ---------------- launch ----------------
extern "C" void kernel_launch(void* const* d_in, const int* in_sizes, int n_in,
                              void* d_out, int out_size) {
    const float* x  = (const float*)d_in[0];
    const int*   ei = (const int*)d_in[1];     // int32 edge index (2 x E)
    const float* W1 = (const float*)d_in[2];
    const float* b1 = (const float*)d_in[3];
    const float* W2 = (const float*)d_in[4];
    const float* b2 = (const float*)d_in[5];
    float* out = (float*)d_out;

    const int nedges = in_sizes[1] / 2;   // 3,200,000
    const int n = NNODES;

    cudaFuncSetAttribute(gemm_tc_kernel<1>,
                         cudaFuncAttributeMaxDynamicSharedMemorySize, GEMM_SMEM_BYTES);
    cudaFuncSetAttribute(gemm_tc_kernel<2>,
                         cudaFuncAttributeMaxDynamicSharedMemorySize, GEMM_SMEM_BYTES);

    zero_kernel<<<(n + 255) / 256, 256>>>(n);
    hist_kernel<<<(nedges / 4 + 255) / 256, 256>>>(ei, nedges);
    scan_kernel<<<NSCAN_BLOCKS, 1024>>>(n);
    fill_kernel<<<(nedges / 4 + 255) / 256, 256>>>(ei, nedges);

    const int gemm_blocks = (n + 127) / 128;      // 782
    const int spmm_blocks = (n * 32 + 255) / 256; // warp per row

    gemm_tc_kernel<1><<<gemm_blocks, 256, GEMM_SMEM_BYTES>>>(x, W1, n);
    spmm_kernel<1><<<spmm_blocks, 256>>>(b1, nullptr, n);
    gemm_tc_kernel<2><<<gemm_blocks, 256, GEMM_SMEM_BYTES>>>(nullptr, W2, n);
    spmm_kernel<2><<<spmm_blocks, 256>>>(b2, out, n);
}

// round 10
// speedup vs baseline: 1.0281x; 1.0281x over previous
#include <cuda_runtime.h>
#include <cuda_fp16.h>
#include <cstdint>

// Problem constants (fixed shapes)
#define NNODES 100000
#define NEDGES 3200000
#define C 128           // feature dim (in = hid = out = 128)
#define NSCAN_BLOCKS ((NNODES + 1023) / 1024)   // 98

// ---------------- scratch (static device globals; no allocation) ----------------
// NOTE on cleanliness invariants: g_cnt and g_scanFlag must be all-zero at entry.
// They are zero-initialized at module load (first call), and every call re-zeroes
// them after use (scan_kernel zeroes g_cnt; fill_kernel zeroes g_scanFlag), so
// every invocation performs identical work on identical state.
__device__ __align__(16) int g_csr[NEDGES];
__device__ __align__(16) int g_rank[NEDGES];
__device__ int    g_cnt[NNODES];
__device__ int    g_rowptr[NNODES + 1];
__device__ int    g_scanAgg[NSCAN_BLOCKS];      // block aggregates
__device__ int    g_scanInc[NSCAN_BLOCKS];      // inclusive prefixes
__device__ int    g_scanFlag[NSCAN_BLOCKS];     // 0=none, 1=agg ready, 2=inclusive ready
__device__ float  g_dinv[NNODES];
__device__ __align__(16) __half g_wt1[C * C];   // W1^T fp16 (n-major)
__device__ __align__(16) __half g_wt2[C * C];   // W2^T fp16 (n-major)
__device__ __align__(16) __half g_h[(size_t)NNODES * C];    // dinv-prescaled GEMM out, fp16
__device__ __align__(16) __half g_buf[(size_t)NNODES * C];  // layer-1 agg+relu out, fp16

// dynamic shared memory for the tensor-core GEMM:
//   Xs  : 128 rows x 136 halves (padded: 272B row stride -> conflict-free ldmatrix)
//   Wts : 128 rows x 136 halves
extern __shared__ __align__(16) __half g_smem[];
#define XS_STRIDE 136
#define WTS_OFF   (128 * XS_STRIDE)
#define GEMM_SMEM_BYTES (2 * 128 * XS_STRIDE * (int)sizeof(__half))

// ---------------- mma helpers ----------------
__device__ __forceinline__ unsigned sptr(const void* p) {
    return (unsigned)__cvta_generic_to_shared(p);
}
__device__ __forceinline__ void ldsm_x4(unsigned& r0, unsigned& r1,
                                        unsigned& r2, unsigned& r3, unsigned addr) {
    asm volatile("ldmatrix.sync.aligned.m8n8.x4.shared.b16 {%0,%1,%2,%3}, [%4];"
                 : "=r"(r0), "=r"(r1), "=r"(r2), "=r"(r3) : "r"(addr));
}
__device__ __forceinline__ void mma16816(float& d0, float& d1, float& d2, float& d3,
                                         unsigned a0, unsigned a1, unsigned a2, unsigned a3,
                                         unsigned b0, unsigned b1) {
    asm volatile(
        "mma.sync.aligned.m16n8k16.row.col.f32.f16.f16.f32 "
        "{%0,%1,%2,%3},{%4,%5,%6,%7},{%8,%9},{%0,%1,%2,%3};"
        : "+f"(d0), "+f"(d1), "+f"(d2), "+f"(d3)
        : "r"(a0), "r"(a1), "r"(a2), "r"(a3), "r"(b0), "r"(b1));
}

// ---------------- prologue kernels ----------------

// histogram of dst degree + per-edge rank (4 edges per thread)
__global__ void hist_kernel(const int* __restrict__ ei, int nedges) {
    int t = blockIdx.x * blockDim.x + threadIdx.x;
    int e = t * 4;
    if (e + 4 <= nedges) {
        int4 d4 = *(const int4*)&ei[nedges + e];
        int4 r4;
        r4.x = atomicAdd(&g_cnt[d4.x], 1);
        r4.y = atomicAdd(&g_cnt[d4.y], 1);
        r4.z = atomicAdd(&g_cnt[d4.z], 1);
        r4.w = atomicAdd(&g_cnt[d4.w], 1);
        *(int4*)&g_rank[e] = r4;
    } else {
        for (int k = e; k < nedges; k++)
            g_rank[k] = atomicAdd(&g_cnt[ei[nedges + k]], 1);
    }
}

// single-pass exclusive scan (decoupled lookback) + dinv + rowptr[n].
// Also self-cleans g_cnt back to 0 for the next invocation.
__global__ __launch_bounds__(1024) void scan_kernel(int n) {
    __shared__ int warp_sums[32];
    __shared__ int s_agg;
    __shared__ int s_prefix;
    const int tid = threadIdx.x, lane = tid & 31, wid = tid >> 5;
    const int b = blockIdx.x;
    const int i = b * 1024 + tid;
    int v = (i < n) ? g_cnt[i] : 0;
    int x = v;
    #pragma unroll
    for (int off = 1; off < 32; off <<= 1) {
        int t = __shfl_up_sync(0xffffffffu, x, off);
        if (lane >= off) x += t;
    }
    if (lane == 31) warp_sums[wid] = x;
    __syncthreads();
    if (wid == 0) {
        int ws = warp_sums[lane];
        #pragma unroll
        for (int off = 1; off < 32; off <<= 1) {
            int t = __shfl_up_sync(0xffffffffu, ws, off);
            if (lane >= off) ws += t;
        }
        warp_sums[lane] = ws;
    }
    __syncthreads();
    int woff = wid ? warp_sums[wid - 1] : 0;
    if (tid == 1023) s_agg = woff + x;   // block total
    __syncthreads();

    if (tid == 0) {
        int agg = s_agg;
        g_scanAgg[b] = agg;
        __threadfence();
        g_scanFlag[b] = 1;
        // decoupled lookback
        int prefix = 0;
        volatile int* flags = g_scanFlag;
        for (int p = b - 1; p >= 0; p--) {
            int f;
            while ((f = flags[p]) == 0) {}
            if (f == 2) { prefix += g_scanInc[p]; break; }
            prefix += g_scanAgg[p];
        }
        g_scanInc[b] = prefix + agg;
        __threadfence();
        g_scanFlag[b] = 2;
        s_prefix = prefix;
    }
    __syncthreads();
    int prefix = s_prefix;
    if (i < n) {
        g_rowptr[i] = prefix + woff + x - v;     // global exclusive
        g_dinv[i] = rsqrtf((float)(v + 1));      // deg = in-deg + self loop
        g_cnt[i] = 0;                            // self-clean for next call
    }
    if (b == gridDim.x - 1 && tid == 1023) g_rowptr[n] = prefix + s_agg;
}

// fill CSR atomic-free using precomputed ranks (4 edges per thread).
// Block 0 also resets the scan flags for the next invocation.
__global__ void fill_kernel(const int* __restrict__ ei, int nedges) {
    if (blockIdx.x == 0 && threadIdx.x < NSCAN_BLOCKS) g_scanFlag[threadIdx.x] = 0;
    int t = blockIdx.x * blockDim.x + threadIdx.x;
    int e = t * 4;
    if (e + 4 <= nedges) {
        int4 s4 = *(const int4*)&ei[e];
        int4 d4 = *(const int4*)&ei[nedges + e];
        int4 r4 = *(const int4*)&g_rank[e];
        g_csr[g_rowptr[d4.x] + r4.x] = s4.x;
        g_csr[g_rowptr[d4.y] + r4.y] = s4.y;
        g_csr[g_rowptr[d4.z] + r4.z] = s4.z;
        g_csr[g_rowptr[d4.w] + r4.w] = s4.w;
    } else {
        for (int k = e; k < nedges; k++)
            g_csr[g_rowptr[ei[nedges + k]] + g_rank[k]] = ei[k];
    }
}

// W1, W2 (fp32 [k][n]) -> g_wt1, g_wt2 (fp16 [n][k]); one launch, 128 blocks.
__global__ void wt_kernel(const float* __restrict__ W1, const float* __restrict__ W2) {
    int i = blockIdx.x * blockDim.x + threadIdx.x;   // 32768 threads
    const float* W = (i < 16384) ? W1 : W2;
    __half* dst = (i < 16384) ? g_wt1 : g_wt2;
    int j = i & 16383;
    int k = j >> 7, n = j & 127;                     // coalesced read
    dst[n * C + k] = __float2half(W[j]);
}

// ---------------- GEMM (tensor core): g_h(fp16) = dinv ⊙ (X @ W) --------------
// Block: 128 rows x 128 cols, K=128 resident. 8 warps: 4 (m) x 2 (n).
template <int LAYER>
__global__ __launch_bounds__(256) void gemm_tc_kernel(
    const float* __restrict__ Xin, int nrows) {
    __half* Xs  = g_smem;            // [128][136]
    __half* Wts = g_smem + WTS_OFF;  // [128][136]  (W^T: [n][k])
    const __half* __restrict__ Wg = (LAYER == 1) ? g_wt1 : g_wt2;
    const int tid  = threadIdx.x;
    const int lane = tid & 31;
    const int wid  = tid >> 5;
    const int row_blk = blockIdx.x * 128;

    // load W^T (fp16, 128x128 halves = 2048 uint4)
    #pragma unroll
    for (int i = tid; i < 2048; i += 256) {
        int r = i >> 4, j = i & 15;
        *(uint4*)&Wts[r * XS_STRIDE + j * 8] = ((const uint4*)Wg)[i];
    }
    // X rows into Xs
    if (LAYER == 1) {
        #pragma unroll
        for (int i = tid; i < 4096; i += 256) {       // 128 rows x 32 float4
            int r = i >> 5, j = i & 31;
            int gr = row_blk + r;
            float4 v = (gr < nrows) ? ((const float4*)&Xin[(size_t)gr * C])[j]
                                    : make_float4(0.f, 0.f, 0.f, 0.f);
            __half2 h0 = __floats2half2_rn(v.x, v.y);
            __half2 h1 = __floats2half2_rn(v.z, v.w);
            uint2 st;
            st.x = *(unsigned*)&h0;
            st.y = *(unsigned*)&h1;
            *(uint2*)&Xs[r * XS_STRIDE + j * 4] = st;
        }
    } else {
        #pragma unroll
        for (int i = tid; i < 2048; i += 256) {       // 128 rows x 16 uint4 (fp16)
            int r = i >> 4, j = i & 15;
            int gr = row_blk + r;
            uint4 v = (gr < nrows) ? *(const uint4*)&g_buf[(size_t)gr * C + j * 8]
                                   : make_uint4(0u, 0u, 0u, 0u);
            *(uint4*)&Xs[r * XS_STRIDE + j * 8] = v;
        }
    }
    __syncthreads();

    const int warp_m = wid & 3;        // 4 m-warps -> 32 rows each
    const int warp_n = wid >> 2;       // 2 n-warps -> 64 cols each
    const int m0 = warp_m * 32;
    const int n0 = warp_n * 64;

    float acc[2][8][4];
    #pragma unroll
    for (int mt = 0; mt < 2; mt++)
        #pragma unroll
        for (int nt = 0; nt < 8; nt++)
            #pragma unroll
            for (int q = 0; q < 4; q++) acc[mt][nt][q] = 0.f;

    #pragma unroll
    for (int ks = 0; ks < 8; ks++) {
        const int k0 = ks * 16;
        unsigned A0[4], A1[4];
        {
            const __half* p0 = &Xs[(m0 + 0 + (lane & 15)) * XS_STRIDE + k0 + (lane >> 4) * 8];
            ldsm_x4(A0[0], A0[1], A0[2], A0[3], sptr(p0));
            const __half* p1 = &Xs[(m0 + 16 + (lane & 15)) * XS_STRIDE + k0 + (lane >> 4) * 8];
            ldsm_x4(A1[0], A1[1], A1[2], A1[3], sptr(p1));
        }
        // B: Wts is [n][k] row-major == ".col" B operand -> NON-trans ldmatrix
        unsigned Bf[8][2];
        #pragma unroll
        for (int np = 0; np < 4; np++) {
            int g = lane >> 3;
            const __half* p = &Wts[(n0 + np * 16 + (g >> 1) * 8 + (lane & 7)) * XS_STRIDE
                                   + k0 + (g & 1) * 8];
            unsigned t0, t1, t2, t3;
            ldsm_x4(t0, t1, t2, t3, sptr(p));
            Bf[2 * np + 0][0] = t0; Bf[2 * np + 0][1] = t1;
            Bf[2 * np + 1][0] = t2; Bf[2 * np + 1][1] = t3;
        }
        #pragma unroll
        for (int nt = 0; nt < 8; nt++) {
            mma16816(acc[0][nt][0], acc[0][nt][1], acc[0][nt][2], acc[0][nt][3],
                     A0[0], A0[1], A0[2], A0[3], Bf[nt][0], Bf[nt][1]);
            mma16816(acc[1][nt][0], acc[1][nt][1], acc[1][nt][2], acc[1][nt][3],
                     A1[0], A1[1], A1[2], A1[3], Bf[nt][0], Bf[nt][1]);
        }
    }

    // epilogue: scale row by dinv, store fp16
    #pragma unroll
    for (int mt = 0; mt < 2; mt++) {
        int r0 = row_blk + m0 + mt * 16 + (lane >> 2);
        int r1 = r0 + 8;
        float di0 = (r0 < nrows) ? g_dinv[r0] : 0.f;
        float di1 = (r1 < nrows) ? g_dinv[r1] : 0.f;
        #pragma unroll
        for (int nt = 0; nt < 8; nt++) {
            int col = n0 + nt * 8 + (lane & 3) * 2;
            if (r0 < nrows) {
                __half2 h = __floats2half2_rn(acc[mt][nt][0] * di0, acc[mt][nt][1] * di0);
                *(unsigned*)&g_h[(size_t)r0 * C + col] = *(unsigned*)&h;
            }
            if (r1 < nrows) {
                __half2 h = __floats2half2_rn(acc[mt][nt][2] * di1, acc[mt][nt][3] * di1);
                *(unsigned*)&g_h[(size_t)r1 * C + col] = *(unsigned*)&h;
            }
        }
    }
}

// ---------------- SpMM: warp-per-destination-row, weight-free gather ----------
// out[d] = dinv[d] * ( sum_{e in row d} h'[src_e] + h'[d] ) + bias
// LAYER=1: writes g_buf fp16 (+relu). LAYER=2: writes param out fp32.
template <int LAYER>
__global__ __launch_bounds__(256) void spmm_kernel(
    const float* __restrict__ bias, float* __restrict__ outp, int n) {
    int warp = (blockIdx.x * blockDim.x + threadIdx.x) >> 5;
    int lane = threadIdx.x & 31;
    if (warp >= n) return;
    const uint2* __restrict__ H2 = (const uint2*)g_h;
    float dd = g_dinv[warp];

    float4 acc;
    {
        uint2 raw = __ldcg(&H2[(size_t)warp * 32 + lane]);  // self loop
        float2 f0 = __half22float2(*(const __half2*)&raw.x);
        float2 f1 = __half22float2(*(const __half2*)&raw.y);
        acc = make_float4(f0.x, f0.y, f1.x, f1.y);
    }
    int e0 = g_rowptr[warp];
    int e1 = g_rowptr[warp + 1];
    int e = e0;
    for (; e + 8 <= e1; e += 8) {
        uint2 r[8];
        #pragma unroll
        for (int j = 0; j < 8; j++) {
            int s = g_csr[e + j];
            r[j] = __ldcg(&H2[(size_t)s * 32 + lane]);
        }
        #pragma unroll
        for (int j = 0; j < 8; j++) {
            float2 f0 = __half22float2(*(const __half2*)&r[j].x);
            float2 f1 = __half22float2(*(const __half2*)&r[j].y);
            acc.x += f0.x; acc.y += f0.y; acc.z += f1.x; acc.w += f1.y;
        }
    }
    for (; e < e1; e++) {
        int s = g_csr[e];
        uint2 raw = __ldcg(&H2[(size_t)s * 32 + lane]);
        float2 f0 = __half22float2(*(const __half2*)&raw.x);
        float2 f1 = __half22float2(*(const __half2*)&raw.y);
        acc.x += f0.x; acc.y += f0.y; acc.z += f1.x; acc.w += f1.y;
    }
    float4 b = ((const float4*)bias)[lane];
    acc.x = acc.x * dd + b.x;
    acc.y = acc.y * dd + b.y;
    acc.z = acc.z * dd + b.z;
    acc.w = acc.w * dd + b.w;
    if (LAYER == 1) {
        acc.x = fmaxf(acc.x, 0.f);
        acc.y = fmaxf(acc.y, 0.f);
        acc.z = fmaxf(acc.z, 0.f);
        acc.w = fmaxf(acc.w, 0.f);
        __half2 h0 = __floats2half2_rn(acc.x, acc.y);
        __half2 h1 = __floats2half2_rn(acc.z, acc.w);
        uint2 st;
        st.x = *(unsigned*)&h0;
        st.y = *(unsigned*)&h1;
        ((uint2*)g_buf)[(size_t)warp * 32 + lane] = st;
    } else {
        ((float4*)outp)[(size_t)warp * 32 + lane] = acc;
    }
}

// ---------------- launch ----------------
extern "C" void kernel_launch(void* const* d_in, const int* in_sizes, int n_in,
                              void* d_out, int out_size) {
    const float* x  = (const float*)d_in[0];
    const int*   ei = (const int*)d_in[1];     // int32 edge index (2 x E)
    const float* W1 = (const float*)d_in[2];
    const float* b1 = (const float*)d_in[3];
    const float* W2 = (const float*)d_in[4];
    const float* b2 = (const float*)d_in[5];
    float* out = (float*)d_out;

    const int nedges = in_sizes[1] / 2;   // 3,200,000
    const int n = NNODES;

    cudaFuncSetAttribute(gemm_tc_kernel<1>,
                         cudaFuncAttributeMaxDynamicSharedMemorySize, GEMM_SMEM_BYTES);
    cudaFuncSetAttribute(gemm_tc_kernel<2>,
                         cudaFuncAttributeMaxDynamicSharedMemorySize, GEMM_SMEM_BYTES);

    hist_kernel<<<(nedges / 4 + 255) / 256, 256>>>(ei, nedges);
    scan_kernel<<<NSCAN_BLOCKS, 1024>>>(n);
    fill_kernel<<<(nedges / 4 + 255) / 256, 256>>>(ei, nedges);
    wt_kernel<<<128, 256>>>(W1, W2);

    const int gemm_blocks = (n + 127) / 128;      // 782
    const int spmm_blocks = (n * 32 + 255) / 256; // warp per row

    gemm_tc_kernel<1><<<gemm_blocks, 256, GEMM_SMEM_BYTES>>>(x, n);
    spmm_kernel<1><<<spmm_blocks, 256>>>(b1, nullptr, n);
    gemm_tc_kernel<2><<<gemm_blocks, 256, GEMM_SMEM_BYTES>>>(nullptr, n);
    spmm_kernel<2><<<spmm_blocks, 256>>>(b2, out, n);
}